// round 11
// baseline (speedup 1.0000x reference)
#include <cuda_runtime.h>
#include <cuda_fp16.h>
#include <cstdint>
#include <math.h>

// ---------------- problem constants ----------------
#define T_TOK   8192
#define D_DIM   1024
#define E_NUM   8
#define FF      4096
#define SHARED_BASE 17408
#define NSLOT       25600            // 200 * 128

#define BM  128
#define BN  256
#define BKS 128                       // superchunk: 2 x 64-col sub-tiles
#define A_SUB 16384
#define B_SUB 32768
#define B_OFF (2 * A_SUB)
#define BUF_B (2 * A_SUB + 2 * B_SUB) // 98304
#define SMEM_TOTAL (2 * BUF_B)        // 196608

// ---------------- scratch ----------------
static __device__ int   g_slot_token [NSLOT];
static __device__ float g_slot_weight[NSLOT];
static __device__ int   g_slot_expert[NSLOT];
static __device__ int   g_counts[E_NUM];
static __device__ int   g_fill  [E_NUM];
static __device__ int   g_aoff  [E_NUM];
static __device__ int   g_tok_idx[T_TOK * 2];
static __device__ float g_tok_w  [T_TOK * 2];

static __device__ __half g_x  [(size_t)T_TOK * D_DIM];
static __device__ __half g_wfc[(size_t)E_NUM * FF * D_DIM];
static __device__ __half g_wpj[(size_t)E_NUM * D_DIM * FF];
static __device__ __half g_sfc[(size_t)FF * D_DIM];
static __device__ __half g_spj[(size_t)D_DIM * FF];
static __device__ __half g_h  [(size_t)NSLOT * FF];

// ---------------- helpers ----------------
__device__ __forceinline__ uint32_t smem_u32(const void* p) {
    uint32_t a;
    asm("{ .reg .u64 t; cvta.to.shared.u64 t, %1; cvt.u32.u64 %0, t; }" : "=r"(a) : "l"(p));
    return a;
}
__device__ __forceinline__ void ldm_x4(uint32_t addr, uint32_t r[4]) {
    asm volatile("ldmatrix.sync.aligned.m8n8.x4.shared.b16 {%0,%1,%2,%3}, [%4];"
                 : "=r"(r[0]), "=r"(r[1]), "=r"(r[2]), "=r"(r[3]) : "r"(addr));
}
__device__ __forceinline__ void mma16816(float d[4], const uint32_t a[4], const uint32_t b[2]) {
    asm volatile("mma.sync.aligned.m16n8k16.row.col.f32.f16.f16.f32 "
                 "{%0,%1,%2,%3}, {%4,%5,%6,%7}, {%8,%9}, {%0,%1,%2,%3};"
                 : "+f"(d[0]), "+f"(d[1]), "+f"(d[2]), "+f"(d[3])
                 : "r"(a[0]), "r"(a[1]), "r"(a[2]), "r"(a[3]), "r"(b[0]), "r"(b[1]));
}
__device__ __forceinline__ void cp16(uint32_t saddr, const void* gaddr, uint32_t src_sz) {
    asm volatile("cp.async.cg.shared.global [%0], [%1], 16, %2;"
                 :: "r"(saddr), "l"(gaddr), "r"(src_sz) : "memory");
}
__device__ __forceinline__ void cp_commit() {
    asm volatile("cp.async.commit_group;" ::: "memory");
}
template <int N>
__device__ __forceinline__ void cp_wait() {
    asm volatile("cp.async.wait_group %0;" :: "n"(N) : "memory");
}

// ---------------- pre-convert: fp32 -> fp16, 4 float4/thread, no tail ----
static __global__ void cvt_hi4(const float4* __restrict__ src,
                               __half* __restrict__ dst) {
    int base = (blockIdx.x * blockDim.x + threadIdx.x) * 4;
    float4 v[4];
#pragma unroll
    for (int j = 0; j < 4; j++) v[j] = src[base + j];
#pragma unroll
    for (int j = 0; j < 4; j++) {
        __half2 h0 = __floats2half2_rn(v[j].x, v[j].y);
        __half2 h1 = __floats2half2_rn(v[j].z, v[j].w);
        *(uint2*)(dst + 4 * (size_t)(base + j)) =
            make_uint2(*reinterpret_cast<uint32_t*>(&h0),
                       *reinterpret_cast<uint32_t*>(&h1));
    }
}

// ---------------- routing kernels ----------------
static __global__ void init_kernel() {
    int s = blockIdx.x * blockDim.x + threadIdx.x;
    if (s < NSLOT) {
        if (s < SHARED_BASE) {
            g_slot_token[s] = -1; g_slot_weight[s] = 0.f; g_slot_expert[s] = 0;
        } else {
            g_slot_token[s] = s - SHARED_BASE; g_slot_weight[s] = 1.f; g_slot_expert[s] = E_NUM;
        }
    }
    if (s < E_NUM) { g_counts[s] = 0; g_fill[s] = 0; }
}

static __global__ void router_kernel(const float* __restrict__ x,
                                     const float* __restrict__ rw) {
    int gwarp = (blockIdx.x * blockDim.x + threadIdx.x) >> 5;
    int lane  = threadIdx.x & 31;
    if (gwarp >= T_TOK) return;
    const float* xr = x + (size_t)gwarp * D_DIM;
    float acc[E_NUM];
#pragma unroll
    for (int e = 0; e < E_NUM; e++) acc[e] = 0.f;
    for (int d = lane; d < D_DIM; d += 32) {
        float xv = xr[d];
#pragma unroll
        for (int e = 0; e < E_NUM; e++) acc[e] += xv * rw[e * D_DIM + d];
    }
#pragma unroll
    for (int e = 0; e < E_NUM; e++)
#pragma unroll
        for (int o = 16; o > 0; o >>= 1)
            acc[e] += __shfl_xor_sync(0xFFFFFFFFu, acc[e], o);
    if (lane == 0) {
        int i1 = 0; float l1 = acc[0];
#pragma unroll
        for (int e = 1; e < E_NUM; e++) if (acc[e] > l1) { l1 = acc[e]; i1 = e; }
        int i2 = -1; float l2 = -INFINITY;
#pragma unroll
        for (int e = 0; e < E_NUM; e++)
            if (e != i1 && acc[e] > l2) { l2 = acc[e]; i2 = e; }
        float w1 = 1.f / (1.f + expf(l2 - l1));
        float w2 = 1.f - w1;
        g_tok_idx[gwarp * 2 + 0] = i1;  g_tok_idx[gwarp * 2 + 1] = i2;
        g_tok_w  [gwarp * 2 + 0] = w1;  g_tok_w  [gwarp * 2 + 1] = w2;
        atomicAdd(&g_counts[i1], 1);    atomicAdd(&g_counts[i2], 1);
    }
}

static __global__ void offsets_kernel() {
    if (blockIdx.x == 0 && threadIdx.x == 0) {
        int off = 0;
#pragma unroll
        for (int e = 0; e < E_NUM; e++) {
            g_aoff[e] = off;
            off = (off + g_counts[e] + 127) & ~127;
        }
    }
}

static __global__ void assign_kernel() {
    int t = blockIdx.x * blockDim.x + threadIdx.x;
    if (t >= T_TOK) return;
#pragma unroll
    for (int k = 0; k < 2; k++) {
        int   e = g_tok_idx[t * 2 + k];
        float w = g_tok_w  [t * 2 + k];
        int pos = atomicAdd(&g_fill[e], 1);
        int s   = g_aoff[e] + pos;
        g_slot_token[s] = t; g_slot_weight[s] = w; g_slot_expert[s] = e;
    }
}

// ---------------- fp16 mma.sync ragged GEMM ----------------
// EPI = 0: fc          -> g_h = relu(x @ Wfc^T)^2   (full slot range)
// EPI = 1: proj shared -> out[tok] = acc            (slots >= SHARED_BASE, w = 1)
// EPI = 2: proj expert -> out[tok] += w * acc       (expert slot range)
template <int KDIM, int EPI>
static __global__ void __launch_bounds__(256, 1)
moe_mma(float* __restrict__ outp)
{
    extern __shared__ __align__(16) char smem[];
    const uint32_t sb = smem_u32(smem);

    const int tid  = threadIdx.x;
    const int wid  = tid >> 5, lane = tid & 31;
    const int wm   = wid >> 2, wn = wid & 3;       // 2 x 4 warp grid, 64x64 tiles
    const int m0   = (EPI == 1 ? SHARED_BASE : 0) + blockIdx.y * BM;
    const int n0   = blockIdx.x * BN;

    // skip fully-padding blocks (padding occupies region tails, so row 0 invalid
    // implies the whole 128-row block is invalid)
    if (EPI != 1 && g_slot_token[m0] < 0) return;

    const int expert = g_slot_expert[m0];
    const __half *A, *B;
    if (EPI == 0) {
        A = g_x;
        B = (expert < E_NUM) ? g_wfc + (size_t)expert * FF * D_DIM : g_sfc;
    } else {
        A = g_h;
        B = (expert < E_NUM) ? g_wpj + (size_t)expert * D_DIM * FF : g_spj;
    }

    // ---- loader mapping ----
    const int lr = tid >> 3;
    const int g  = tid & 7;
    const __half* aP[4];
    uint32_t asz[4];
#pragma unroll
    for (int p = 0; p < 4; p++) {
        int slot = m0 + lr + 32 * p;
        if (EPI == 0) {
            int tok = g_slot_token[slot];
            asz[p] = (tok >= 0) ? 16u : 0u;
            aP[p]  = A + (size_t)(tok >= 0 ? tok : 0) * KDIM;
        } else {
            asz[p] = 16u;
            aP[p]  = A + (size_t)slot * KDIM;
        }
    }
    const __half* bBase = B + (size_t)(n0 + lr) * KDIM;
    const uint32_t soff0 = (uint32_t)lr * 128
                         + (((uint32_t)g * 16) ^ (((uint32_t)lr & 7) * 16));

    // ---- ldmatrix lane addressing ----
    const uint32_t preA0 = (uint32_t)(wm * 64 + (lane & 15)) * 128;
    const uint32_t xvA   = ((uint32_t)lane & 7) * 16;
    const uint32_t cA    = ((uint32_t)lane >> 4) * 16;
    const uint32_t preB0 = (uint32_t)(wn * 64 + (lane & 7) + (((uint32_t)lane >> 4) << 3)) * 128;
    const uint32_t xvB   = ((uint32_t)lane & 7) * 16;
    const uint32_t cB    = (((uint32_t)lane >> 3) & 1) * 16;

    float acc[4][8][4];
#pragma unroll
    for (int mt = 0; mt < 4; mt++)
#pragma unroll
        for (int nt = 0; nt < 8; nt++)
#pragma unroll
            for (int j = 0; j < 4; j++) acc[mt][nt][j] = 0.f;

    auto issue_super = [&](int sc) {
        const uint32_t bb = sb + (uint32_t)(sc & 1) * BUF_B;
#pragma unroll
        for (int sub = 0; sub < 2; sub++) {
            const int kb = sc * BKS + sub * 64 + g * 8;
#pragma unroll
            for (int p = 0; p < 4; p++)
                cp16(bb + sub * A_SUB + soff0 + p * 4096, aP[p] + kb, asz[p]);
#pragma unroll
            for (int p = 0; p < 8; p++)
                cp16(bb + B_OFF + sub * B_SUB + soff0 + p * 4096,
                     bBase + (size_t)p * 32 * KDIM + kb, 16u);
        }
    };

    auto mma_super = [&](uint32_t bb) {
#pragma unroll
        for (int kk = 0; kk < 8; kk++) {
            const uint32_t aSub = bb + (kk >> 2) * A_SUB;
            const uint32_t bSub = bb + B_OFF + (kk >> 2) * B_SUB;
            const uint32_t kb = (uint32_t)(kk & 3) * 32;
            uint32_t ah[4][4], bh[8][2];
#pragma unroll
            for (int mt = 0; mt < 4; mt++)
                ldm_x4(aSub + preA0 + mt * 2048 + ((cA + kb) ^ xvA), ah[mt]);
#pragma unroll
            for (int p = 0; p < 4; p++) {
                uint32_t t[4];
                ldm_x4(bSub + preB0 + p * 2048 + ((cB + kb) ^ xvB), t);
                bh[2*p][0] = t[0]; bh[2*p][1] = t[1];
                bh[2*p+1][0] = t[2]; bh[2*p+1][1] = t[3];
            }
#pragma unroll
            for (int mt = 0; mt < 4; mt++)
#pragma unroll
                for (int nt = 0; nt < 8; nt++)
                    mma16816(acc[mt][nt], ah[mt], bh[nt]);
        }
    };

    const int NSC = KDIM / BKS;
    issue_super(0);
    cp_commit();
    for (int sc = 0; sc < NSC; sc++) {
        cp_wait<0>();
        __syncthreads();
        if (sc + 1 < NSC) {
            issue_super(sc + 1);
            cp_commit();
        }
        mma_super(sb + (uint32_t)(sc & 1) * BUF_B);
    }

    // ---------------- epilogue ----------------
    const int qn = 2 * (lane & 3);
#pragma unroll
    for (int mt = 0; mt < 4; mt++) {
#pragma unroll
        for (int half = 0; half < 2; half++) {
            const int row  = wm * 64 + mt * 16 + (lane >> 2) + 8 * half;
            const int slot = m0 + row;
            if (EPI == 0) {
                const size_t base = (size_t)slot * FF + n0 + wn * 64 + qn;
#pragma unroll
                for (int nt = 0; nt < 8; nt++) {
                    float v0 = fmaxf(acc[mt][nt][2 * half + 0], 0.f); v0 *= v0;
                    float v1 = fmaxf(acc[mt][nt][2 * half + 1], 0.f); v1 *= v1;
                    __half2 h = __floats2half2_rn(v0, v1);
                    *(uint32_t*)&g_h[base + nt * 8] = *reinterpret_cast<uint32_t*>(&h);
                }
            } else if (EPI == 1) {
                const int tok = slot - SHARED_BASE;          // always valid, w = 1
                float* orow = outp + (size_t)tok * D_DIM + n0 + wn * 64 + qn;
#pragma unroll
                for (int nt = 0; nt < 8; nt++) {
                    orow[nt * 8 + 0] = acc[mt][nt][2 * half + 0];
                    orow[nt * 8 + 1] = acc[mt][nt][2 * half + 1];
                }
            } else {
                const int   tok = g_slot_token[slot];
                const float w   = g_slot_weight[slot];
                if (tok >= 0) {
                    float* orow = outp + (size_t)tok * D_DIM + n0 + wn * 64 + qn;
#pragma unroll
                    for (int nt = 0; nt < 8; nt++) {
                        atomicAdd(orow + nt * 8 + 0, w * acc[mt][nt][2 * half + 0]);
                        atomicAdd(orow + nt * 8 + 1, w * acc[mt][nt][2 * half + 1]);
                    }
                }
            }
        }
    }
}

// ---------------- launch ----------------
extern "C" void kernel_launch(void* const* d_in, const int* in_sizes, int n_in,
                              void* d_out, int out_size) {
    const float* x     = (const float*)d_in[0];
    const float* rw    = (const float*)d_in[1];
    const float* wfc   = (const float*)d_in[2];
    const float* wproj = (const float*)d_in[3];
    const float* sfc   = (const float*)d_in[4];
    const float* sproj = (const float*)d_in[5];
    float* out = (float*)d_out;

    cudaFuncSetAttribute(moe_mma<D_DIM, 0>,
                         cudaFuncAttributeMaxDynamicSharedMemorySize, SMEM_TOTAL);
    cudaFuncSetAttribute(moe_mma<FF, 1>,
                         cudaFuncAttributeMaxDynamicSharedMemorySize, SMEM_TOTAL);
    cudaFuncSetAttribute(moe_mma<FF, 2>,
                         cudaFuncAttributeMaxDynamicSharedMemorySize, SMEM_TOTAL);

    __half *xh, *fh, *ph, *sh, *qh;
    cudaGetSymbolAddress((void**)&xh, g_x);
    cudaGetSymbolAddress((void**)&fh, g_wfc);
    cudaGetSymbolAddress((void**)&ph, g_wpj);
    cudaGetSymbolAddress((void**)&sh, g_sfc);
    cudaGetSymbolAddress((void**)&qh, g_spj);

    const int n4_x  = T_TOK * D_DIM / 4;          // 2M, /4 per thread
    const int n4_w  = E_NUM * FF * D_DIM / 4;     // 8M
    const int n4_s  = FF * D_DIM / 4;             // 1M
    cvt_hi4<<<n4_x / 4 / 256, 256>>>((const float4*)x,     xh);
    cvt_hi4<<<n4_w / 4 / 256, 256>>>((const float4*)wfc,   fh);
    cvt_hi4<<<n4_w / 4 / 256, 256>>>((const float4*)wproj, ph);
    cvt_hi4<<<n4_s / 4 / 256, 256>>>((const float4*)sfc,   sh);
    cvt_hi4<<<n4_s / 4 / 256, 256>>>((const float4*)sproj, qh);

    init_kernel<<<(NSLOT + 255) / 256, 256>>>();
    router_kernel<<<T_TOK / 8, 256>>>(x, rw);
    offsets_kernel<<<1, 32>>>();
    assign_kernel<<<T_TOK / 256, 256>>>();

    // GEMM1: h = relu(gathered_x @ Wfc^T)^2 over all slots
    moe_mma<D_DIM, 0><<<dim3(FF / BN, NSLOT / BM), 256, SMEM_TOTAL>>>(nullptr);
    // GEMM2a: shared expert writes out directly (covers every token once)
    moe_mma<FF, 1><<<dim3(D_DIM / BN, T_TOK / BM), 256, SMEM_TOTAL>>>(out);
    // GEMM2b: routed experts accumulate on top
    moe_mma<FF, 2><<<dim3(D_DIM / BN, SHARED_BASE / BM), 256, SMEM_TOTAL>>>(out);
}